// round 15
// baseline (speedup 1.0000x reference)
#include <cuda_runtime.h>
#include <math.h>
#include <stdint.h>

#define NFULL 6144
#define DF    320
#define NL1   4915
#define NL2   2949
#define NNZ_CAP 2000000
#define SORT_N 8192
#define FULL_MASK 0xffffffffu

// ---------------- device scratch ----------------
__device__ __align__(128) float g_XA[NFULL*DF];
__device__ __align__(128) float g_XB[NFULL*DF];
__device__ __align__(128) float g_XC[NFULL*DF];
__device__ __align__(128) float g_H [NFULL*DF];
__device__ __align__(128) float g_CAT[NFULL*2*DF];
__device__ __align__(128) float g_ORG[NFULL*DF];
__device__ __align__(128) float g_D0[NFULL*DF];
__device__ __align__(128) float g_D1[NL1*DF];
__device__ float g_SV[NFULL];
__device__ float g_TV[NFULL];
__device__ float g_SC[NFULL];
__device__ float g_VAL[NL1];

__device__ int g_RP0[NFULL+1];
__device__ int g_C0[NNZ_CAP];
__device__ int g_RP1A[NL1+1];
__device__ int g_C1A[NNZ_CAP];
__device__ int g_RP1B[NL1+1];
__device__ int g_C1B[NNZ_CAP];
__device__ int g_RP2[NL2+1];
__device__ int g_C2[NNZ_CAP];
__device__ int g_I1P1[NL1];
__device__ int g_I2P1[NL2];
__device__ int g_IT1[NL1];
__device__ int g_IT2[NL2];
__device__ int g_POS[NFULL];

// ---------------- helpers ----------------
__device__ __forceinline__ float warpSum(float v){
#pragma unroll
    for (int o = 16; o; o >>= 1) v += __shfl_xor_sync(FULL_MASK, v, o);
    return v;
}
__device__ __forceinline__ float warpMax(float v){
#pragma unroll
    for (int o = 16; o; o >>= 1) v = fmaxf(v, __shfl_xor_sync(FULL_MASK, v, o));
    return v;
}
__device__ __forceinline__ int warpSumI(int v){
#pragma unroll
    for (int o = 16; o; o >>= 1) v += __shfl_xor_sync(FULL_MASK, v, o);
    return v;
}

// ---------------- CSR build from dense A ----------------
__global__ void k_count0(const float* __restrict__ A, int* __restrict__ cnt){
    int row = blockIdx.x;
    int tid = threadIdx.x;
    const float4* Ar = reinterpret_cast<const float4*>(A + (size_t)row * NFULL);
    int c = 0;
    for (int j = tid; j < NFULL/4; j += 256){
        float4 v = __ldg(&Ar[j]);
        c += (v.x > 0.f) + (v.y > 0.f) + (v.z > 0.f) + (v.w > 0.f);
    }
    c = warpSumI(c);
    __shared__ int sh[8];
    int lane = tid & 31, wid = tid >> 5;
    if (lane == 0) sh[wid] = c;
    __syncthreads();
    if (tid == 0){
        int t = 0;
        for (int i = 0; i < 8; i++) t += sh[i];
        cnt[row] = t;
    }
}

// single-block exclusive scan in place; a[n] = total
__global__ void k_scan(int* a, int n){
    __shared__ int sh[1024];
    __shared__ int carry;
    int tid = threadIdx.x;
    if (tid == 0) carry = 0;
    __syncthreads();
    for (int base = 0; base < n; base += 1024){
        int i = base + tid;
        int v = (i < n) ? a[i] : 0;
        sh[tid] = v;
        __syncthreads();
        for (int off = 1; off < 1024; off <<= 1){
            int t = (tid >= off) ? sh[tid - off] : 0;
            __syncthreads();
            sh[tid] += t;
            __syncthreads();
        }
        if (i < n) a[i] = carry + sh[tid] - v;
        int tot = sh[1023];
        __syncthreads();
        if (tid == 0) carry += tot;
        __syncthreads();
    }
    if (tid == 0) a[n] = carry;
}

__global__ void k_fill0(const float* __restrict__ A, const int* __restrict__ rp, int* __restrict__ cols){
    int row = blockIdx.x;
    int lane = threadIdx.x;
    int base = rp[row];
    const float* Ar = A + (size_t)row * NFULL;
    for (int j0 = 0; j0 < NFULL; j0 += 32){
        int j = j0 + lane;
        bool pred = Ar[j] > 0.f;
        unsigned m = __ballot_sync(FULL_MASK, pred);
        if (pred) cols[base + __popc(m & ((1u << lane) - 1u))] = j;
        base += __popc(m);
    }
}

// ---------------- pooled CSR ----------------
__global__ void k_pcount(const int* __restrict__ rpp, const int* __restrict__ colsp,
                         const int* __restrict__ idx, const int* __restrict__ pos,
                         int* __restrict__ cnt){
    int r = blockIdx.x;
    int lane = threadIdx.x;
    int pr = idx[r];
    int s = rpp[pr], e = rpp[pr+1];
    int c = 0;
    for (int i = s + lane; i < e; i += 32) c += (pos[colsp[i]] >= 0);
    c = warpSumI(c);
    if (lane == 0) cnt[r] = c;
}

__global__ void k_pfill(const int* __restrict__ rpp, const int* __restrict__ colsp,
                        const int* __restrict__ idx, const int* __restrict__ pos,
                        const int* __restrict__ rpn, int* __restrict__ colsn){
    int r = blockIdx.x;
    int lane = threadIdx.x;
    int pr = idx[r];
    int s = rpp[pr], e = rpp[pr+1];
    int base = rpn[r];
    for (int i0 = s; i0 < e; i0 += 32){
        int i = i0 + lane;
        int p = -1;
        bool pred = false;
        if (i < e){ p = pos[colsp[i]]; pred = (p >= 0); }
        unsigned m = __ballot_sync(FULL_MASK, pred);
        if (pred) colsn[base + __popc(m & ((1u << lane) - 1u))] = p;
        base += __popc(m);
    }
}

// ---------------- GEMM: C[Mx320] = A[MxK]*B[Kx320] (+bias)(+res) ----------------
__global__ __launch_bounds__(256) void k_gemm(const float* __restrict__ A, const float* __restrict__ B,
                                              const float* __restrict__ bias, const float* __restrict__ res,
                                              float* __restrict__ C, int M, int K){
    __shared__ float As[16][64];
    __shared__ float Bs[16][64];
    int tid = threadIdx.x;
    int bm = blockIdx.y * 64, bn = blockIdx.x * 64;
    int tx = tid & 15, ty = tid >> 4;
    int a_m = tid >> 2;
    int a_k = (tid & 3) * 4;
    int b_k = tid >> 4;
    int b_n = (tid & 15) * 4;
    float acc[4][4];
#pragma unroll
    for (int r = 0; r < 4; r++)
#pragma unroll
        for (int c = 0; c < 4; c++) acc[r][c] = 0.f;

    for (int k0 = 0; k0 < K; k0 += 16){
        float4 av = make_float4(0.f,0.f,0.f,0.f);
        if (bm + a_m < M)
            av = *reinterpret_cast<const float4*>(&A[(size_t)(bm + a_m) * K + k0 + a_k]);
        As[a_k+0][a_m] = av.x; As[a_k+1][a_m] = av.y;
        As[a_k+2][a_m] = av.z; As[a_k+3][a_m] = av.w;
        float4 bv = *reinterpret_cast<const float4*>(&B[(size_t)(k0 + b_k) * 320 + bn + b_n]);
        *reinterpret_cast<float4*>(&Bs[b_k][b_n]) = bv;
        __syncthreads();
#pragma unroll
        for (int kk = 0; kk < 16; kk++){
            float4 a4 = *reinterpret_cast<const float4*>(&As[kk][ty*4]);
            float4 b4 = *reinterpret_cast<const float4*>(&Bs[kk][tx*4]);
            acc[0][0] += a4.x*b4.x; acc[0][1] += a4.x*b4.y; acc[0][2] += a4.x*b4.z; acc[0][3] += a4.x*b4.w;
            acc[1][0] += a4.y*b4.x; acc[1][1] += a4.y*b4.y; acc[1][2] += a4.y*b4.z; acc[1][3] += a4.y*b4.w;
            acc[2][0] += a4.z*b4.x; acc[2][1] += a4.z*b4.y; acc[2][2] += a4.z*b4.z; acc[2][3] += a4.z*b4.w;
            acc[3][0] += a4.w*b4.x; acc[3][1] += a4.w*b4.y; acc[3][2] += a4.w*b4.z; acc[3][3] += a4.w*b4.w;
        }
        __syncthreads();
    }
    float4 bb = make_float4(0.f,0.f,0.f,0.f);
    if (bias) bb = *reinterpret_cast<const float4*>(&bias[bn + tx*4]);
#pragma unroll
    for (int r = 0; r < 4; r++){
        int row = bm + ty*4 + r;
        if (row < M){
            float4 o;
            o.x = acc[r][0] + bb.x; o.y = acc[r][1] + bb.y;
            o.z = acc[r][2] + bb.z; o.w = acc[r][3] + bb.w;
            if (res){
                float4 rr = *reinterpret_cast<const float4*>(&res[(size_t)row * 320 + bn + tx*4]);
                o.x += rr.x; o.y += rr.y; o.z += rr.z; o.w += rr.w;
            }
            *reinterpret_cast<float4*>(&C[(size_t)row * 320 + bn + tx*4]) = o;
        }
    }
}

// ---------------- SpMM: Y[i,:] = sum_{j in nbr(i)} X[j,:] ----------------
__global__ __launch_bounds__(320) void k_spmm(const int* __restrict__ rp, const int* __restrict__ cols,
                                              const float* __restrict__ X, float* __restrict__ Y){
    int row = blockIdx.x;
    int s = rp[row], e = rp[row+1];
    int tid = threadIdx.x;
    __shared__ int cbuf[256];
    float acc0 = 0.f, acc1 = 0.f;
    for (int c0 = s; c0 < e; c0 += 256){
        int cc = min(256, e - c0);
        __syncthreads();
        for (int i = tid; i < cc; i += 320) cbuf[i] = cols[c0 + i];
        __syncthreads();
        int i = 0;
        for (; i + 1 < cc; i += 2){
            acc0 += X[(size_t)cbuf[i]   * 320 + tid];
            acc1 += X[(size_t)cbuf[i+1] * 320 + tid];
        }
        if (i < cc) acc0 += X[(size_t)cbuf[i] * 320 + tid];
    }
    Y[(size_t)row * 320 + tid] = acc0 + acc1;
}

// ---------------- GAT s,t ----------------
__global__ __launch_bounds__(256) void k_st(const float* __restrict__ h, const float* __restrict__ a,
                                            float* __restrict__ sv, float* __restrict__ tv){
    int row = blockIdx.x;
    int tid = threadIdx.x;
    float ps = 0.f, pt = 0.f;
    for (int f = tid; f < 320; f += 256){
        float v = h[(size_t)row * 320 + f];
        ps += v * a[f];
        pt += v * a[320 + f];
    }
    ps = warpSum(ps); pt = warpSum(pt);
    __shared__ float sh[16];
    int lane = tid & 31, wid = tid >> 5;
    if (lane == 0){ sh[wid] = ps; sh[8 + wid] = pt; }
    __syncthreads();
    if (tid == 0){
        float x = 0.f, y = 0.f;
        for (int i = 0; i < 8; i++){ x += sh[i]; y += sh[8 + i]; }
        sv[row] = x; tv[row] = y;
    }
}

// ------------- fused masked softmax + attn@h + elu -------------
__global__ __launch_bounds__(320) void k_gat(const int* __restrict__ rp, const int* __restrict__ cols,
                                             const float* __restrict__ h, const float* __restrict__ sv,
                                             const float* __restrict__ tv, float* __restrict__ out){
    int row = blockIdx.x;
    int s = rp[row], e = rp[row+1];
    int tid = threadIdx.x;
    int lane = tid & 31, wid = tid >> 5;
    __shared__ float sred[12];
    __shared__ float wbuf[256];
    __shared__ int   cbuf[256];
    float si = sv[row];

    // phase 1: row max
    float m = -1e30f;
    for (int i = s + tid; i < e; i += 320){
        float x = si + tv[cols[i]];
        x = x > 0.f ? x : 0.2f * x;
        m = fmaxf(m, x);
    }
    m = warpMax(m);
    if (lane == 0) sred[wid] = m;
    __syncthreads();
    if (tid == 0){
        float mm = sred[0];
        for (int i = 1; i < 10; i++) mm = fmaxf(mm, sred[i]);
        sred[10] = mm;
    }
    __syncthreads();
    m = sred[10];
    __syncthreads();

    // phase 2: denominator
    float sm = 0.f;
    for (int i = s + tid; i < e; i += 320){
        float x = si + tv[cols[i]];
        x = x > 0.f ? x : 0.2f * x;
        sm += expf(x - m);
    }
    sm = warpSum(sm);
    if (lane == 0) sred[wid] = sm;
    __syncthreads();
    if (tid == 0){
        float z = 0.f;
        for (int i = 0; i < 10; i++) z += sred[i];
        sred[10] = z;
    }
    __syncthreads();
    float invZ = 1.f / sred[10];

    // phase 3: weighted gather
    float acc = 0.f;
    for (int c0 = s; c0 < e; c0 += 256){
        int cc = min(256, e - c0);
        __syncthreads();
        for (int i = tid; i < cc; i += 320){
            int c = cols[c0 + i];
            cbuf[i] = c;
            float x = si + tv[c];
            x = x > 0.f ? x : 0.2f * x;
            wbuf[i] = expf(x - m);
        }
        __syncthreads();
        for (int i = 0; i < cc; i++)
            acc += wbuf[i] * h[(size_t)cbuf[i] * 320 + tid];
    }
    float y = acc * invZ;
    out[(size_t)row * 320 + tid] = y > 0.f ? y : expm1f(y);
}

// ---------------- pooling ----------------
__global__ void k_score(const float* __restrict__ X, const float* __restrict__ w,
                        const float* __restrict__ b, float* __restrict__ sc, int M){
    int row = blockIdx.x * 8 + (threadIdx.x >> 5);
    int lane = threadIdx.x & 31;
    if (row >= M) return;
    float s = 0.f;
    for (int f = lane; f < 320; f += 32) s += X[(size_t)row * 320 + f] * w[f];
    s = warpSum(s);
    if (lane == 0) sc[row] = 1.f / (1.f + expf(-(s + b[0]) / 100.f));
}

__global__ void k_sort_topk(const float* __restrict__ scores, int n, int knum,
                            int* __restrict__ idx, float* __restrict__ vals){
    extern __shared__ unsigned long long key[];
    int tid = threadIdx.x;
    for (int i = tid; i < SORT_N; i += 1024){
        unsigned long long k = 0ull;
        if (i < n){
            unsigned hi = __float_as_uint(scores[i]);   // sigmoid > 0 -> uint-monotone
            k = ((unsigned long long)hi << 32) | (unsigned)(0xFFFFFFFFu - i);
        }
        key[i] = k;
    }
    __syncthreads();
    for (int kk = 2; kk <= SORT_N; kk <<= 1){
        for (int j = kk >> 1; j > 0; j >>= 1){
            for (int i = tid; i < SORT_N; i += 1024){
                int ixj = i ^ j;
                if (ixj > i){
                    bool dir = ((i & kk) != 0);  // descending overall
                    unsigned long long a = key[i], b = key[ixj];
                    if ((a > b) == dir){ key[i] = b; key[ixj] = a; }
                }
            }
            __syncthreads();
        }
    }
    for (int r = tid; r < knum; r += 1024){
        unsigned long long k = key[r];
        idx[r]  = (int)(0xFFFFFFFFu - (unsigned)(k & 0xFFFFFFFFu));
        vals[r] = __uint_as_float((unsigned)(k >> 32));
    }
}

__global__ void k_gate(const float* __restrict__ X, const int* __restrict__ idx,
                       const float* __restrict__ vals, float* __restrict__ Y){
    int r = blockIdx.x, f = threadIdx.x;
    Y[(size_t)r * 320 + f] = X[(size_t)idx[r] * 320 + f] * vals[r];
}

__global__ void k_ineg(int* p, int n){
    int i = blockIdx.x * 256 + threadIdx.x;
    if (i < n) p[i] = -1;
}
__global__ void k_setpos(const int* __restrict__ idx, int* __restrict__ p, int k){
    int i = blockIdx.x * 256 + threadIdx.x;
    if (i < k) p[idx[i]] = i;
}
__global__ void k_zero(float* p, int n){
    int i = blockIdx.x * 256 + threadIdx.x;
    if (i < n) p[i] = 0.f;
}
__global__ void k_scatter(const float* __restrict__ X, const int* __restrict__ idx,
                          float* __restrict__ Y){
    int r = blockIdx.x, f = threadIdx.x;
    Y[(size_t)idx[r] * 320 + f] = X[(size_t)r * 320 + f];
}
__global__ void k_copyf(const float* __restrict__ s, float* __restrict__ d, int n){
    int i = blockIdx.x * 256 + threadIdx.x;
    if (i < n) d[i] = s[i];
}
__global__ void k_copyi(const int* __restrict__ s, int* __restrict__ d, int n){
    int i = blockIdx.x * 256 + threadIdx.x;
    if (i < n) d[i] = s[i];
}
__global__ void k_concat(const float* __restrict__ X, const float* __restrict__ O,
                         float* __restrict__ C){
    int r = blockIdx.x, f = threadIdx.x;
    C[(size_t)r * 640 + f]       = X[(size_t)r * 320 + f];
    C[(size_t)r * 640 + 320 + f] = O[(size_t)r * 320 + f];
}

// ---------------- orchestration ----------------
static void gemm(const float* A, const float* B, const float* bias, const float* res,
                 float* C, int M, int K){
    dim3 g(5, (M + 63) / 64);
    k_gemm<<<g, 256>>>(A, B, bias, res, C, M, K);
}

extern "C" void kernel_launch(void* const* d_in, const int* in_sizes, int n_in,
                              void* d_out, int out_size) {
    const float* Aden  = (const float*)d_in[0];
    const float* Xin   = (const float*)d_in[1];
    const float* sg_W  = (const float*)d_in[2];
    const float* sg_a  = (const float*)d_in[3];
    const float* bg_W  = (const float*)d_in[4];
    const float* bg_a  = (const float*)d_in[5];
    const float* eg_W  = (const float*)d_in[6];
    const float* eg_a  = (const float*)d_in[7];
    const float* dn_W  = (const float*)d_in[8];
    const float* dn_b  = (const float*)d_in[9];
    const float* up_W  = (const float*)d_in[10];
    const float* up_b  = (const float*)d_in[11];
    const float* pl_w  = (const float*)d_in[12];
    const float* pl_b  = (const float*)d_in[13];
    float* out = (float*)d_out;

    void* p;
    cudaGetSymbolAddress(&p, g_XA);  float* XA = (float*)p;
    cudaGetSymbolAddress(&p, g_XB);  float* XB = (float*)p;
    cudaGetSymbolAddress(&p, g_XC);  float* XC = (float*)p;
    cudaGetSymbolAddress(&p, g_H);   float* H  = (float*)p;
    cudaGetSymbolAddress(&p, g_CAT); float* CAT = (float*)p;
    cudaGetSymbolAddress(&p, g_ORG); float* ORG = (float*)p;
    cudaGetSymbolAddress(&p, g_D0);  float* D0 = (float*)p;
    cudaGetSymbolAddress(&p, g_D1);  float* D1 = (float*)p;
    cudaGetSymbolAddress(&p, g_SV);  float* SV = (float*)p;
    cudaGetSymbolAddress(&p, g_TV);  float* TV = (float*)p;
    cudaGetSymbolAddress(&p, g_SC);  float* SC = (float*)p;
    cudaGetSymbolAddress(&p, g_VAL); float* VAL = (float*)p;
    cudaGetSymbolAddress(&p, g_RP0); int* RP0 = (int*)p;
    cudaGetSymbolAddress(&p, g_C0);  int* C0  = (int*)p;
    cudaGetSymbolAddress(&p, g_RP1A);int* RP1A = (int*)p;
    cudaGetSymbolAddress(&p, g_C1A); int* C1A = (int*)p;
    cudaGetSymbolAddress(&p, g_RP1B);int* RP1B = (int*)p;
    cudaGetSymbolAddress(&p, g_C1B); int* C1B = (int*)p;
    cudaGetSymbolAddress(&p, g_RP2); int* RP2 = (int*)p;
    cudaGetSymbolAddress(&p, g_C2);  int* C2  = (int*)p;
    cudaGetSymbolAddress(&p, g_I1P1);int* I1P1 = (int*)p;
    cudaGetSymbolAddress(&p, g_I2P1);int* I2P1 = (int*)p;
    cudaGetSymbolAddress(&p, g_IT1); int* IT1 = (int*)p;
    cudaGetSymbolAddress(&p, g_IT2); int* IT2 = (int*)p;
    cudaGetSymbolAddress(&p, g_POS); int* POS = (int*)p;

    cudaFuncSetAttribute(k_sort_topk, cudaFuncAttributeMaxDynamicSharedMemorySize,
                         SORT_N * (int)sizeof(unsigned long long));

    const int FE = NFULL * DF;              // full feature count
    const int E1 = NL1 * DF, E2 = NL2 * DF;
    #define CG(n) (((n) + 255) / 256)

    // CSR of full A
    k_count0<<<NFULL, 256>>>(Aden, RP0);
    k_scan<<<1, 1024>>>(RP0, NFULL);
    k_fill0<<<NFULL, 32>>>(Aden, RP0, C0);

    // start GAT (sg)
    gemm(Xin, sg_W, nullptr, nullptr, H, NFULL, 320);
    k_st<<<NFULL, 256>>>(H, sg_a, SV, TV);
    k_gat<<<NFULL, 320>>>(RP0, C0, H, SV, TV, XA);
    k_copyf<<<CG(FE), 256>>>(XA, ORG, FE);

    for (int pass = 0; pass < 2; pass++){
        int* RP1 = pass == 0 ? RP1A : RP1B;
        int* C1  = pass == 0 ? C1A  : C1B;

        // ---- down level 0 (full) ----
        k_spmm<<<NFULL, 320>>>(RP0, C0, XA, XB);
        gemm(XB, dn_W, dn_b, nullptr, XC, NFULL, 320);
        if (pass == 0) k_copyf<<<CG(FE), 256>>>(XC, D0, FE);

        // pool 1: k=0.8 over 6144 -> 4915
        k_score<<<CG(NFULL*32)/1, 256>>>(XC, pl_w, pl_b, SC, NFULL);
        k_sort_topk<<<1, 1024, SORT_N*sizeof(unsigned long long)>>>(SC, NFULL, NL1, IT1, VAL);
        if (pass == 0) k_copyi<<<CG(NL1), 256>>>(IT1, I1P1, NL1);
        k_gate<<<NL1, 320>>>(XC, IT1, VAL, XA);
        k_ineg<<<CG(NFULL), 256>>>(POS, NFULL);
        k_setpos<<<CG(NL1), 256>>>(IT1, POS, NL1);
        k_pcount<<<NL1, 32>>>(RP0, C0, IT1, POS, RP1);
        k_scan<<<1, 1024>>>(RP1, NL1);
        k_pfill<<<NL1, 32>>>(RP0, C0, IT1, POS, RP1, C1);

        // ---- down level 1 ----
        k_spmm<<<NL1, 320>>>(RP1, C1, XA, XB);
        gemm(XB, dn_W + 320*320, dn_b + 320, nullptr, XC, NL1, 320);
        if (pass == 0) k_copyf<<<CG(E1), 256>>>(XC, D1, E1);

        // pool 2: k=0.6 over 4915 -> 2949
        k_score<<<CG(NL1*32)/1, 256>>>(XC, pl_w + 320, pl_b + 1, SC, NL1);
        k_sort_topk<<<1, 1024, SORT_N*sizeof(unsigned long long)>>>(SC, NL1, NL2, IT2, VAL);
        if (pass == 0) k_copyi<<<CG(NL2), 256>>>(IT2, I2P1, NL2);
        k_gate<<<NL2, 320>>>(XC, IT2, VAL, XA);
        k_ineg<<<CG(NL1), 256>>>(POS, NL1);
        k_setpos<<<CG(NL2), 256>>>(IT2, POS, NL2);
        k_pcount<<<NL2, 32>>>(RP1, C1, IT2, POS, RP2);
        k_scan<<<1, 1024>>>(RP2, NL2);
        k_pfill<<<NL2, 32>>>(RP1, C1, IT2, POS, RP2, C2);

        // ---- bottom GAT (bg) ----
        gemm(XA, bg_W, nullptr, nullptr, H, NL2, 320);
        k_st<<<NL2, 256>>>(H, bg_a, SV, TV);
        k_gat<<<NL2, 320>>>(RP2, C2, H, SV, TV, XB);

        // ---- up i=0 (uses pass-1 level-1 structures) ----
        k_zero<<<CG(E1), 256>>>(XA, E1);
        k_scatter<<<NL2, 320>>>(XB, I2P1, XA);
        k_spmm<<<NL1, 320>>>(RP1A, C1A, XA, XC);
        gemm(XC, up_W, up_b, D1, XB, NL1, 320);

        // ---- up i=1 (full) ----
        k_zero<<<CG(FE), 256>>>(XA, FE);
        k_scatter<<<NL1, 320>>>(XB, I1P1, XA);
        k_spmm<<<NFULL, 320>>>(RP0, C0, XA, XC);
        gemm(XC, up_W + 320*320, up_b + 320, D0, XB, NFULL, 320);

        // ---- concat + end GAT (eg) ----
        k_concat<<<NFULL, 320>>>(XB, ORG, CAT);
        gemm(CAT, eg_W, nullptr, nullptr, H, NFULL, 640);
        k_st<<<NFULL, 256>>>(H, eg_a, SV, TV);
        k_gat<<<NFULL, 320>>>(RP0, C0, H, SV, TV, XA);
    }

    // outputs: (X, start)
    k_copyf<<<CG(FE), 256>>>(XA, out, FE);
    k_copyf<<<CG(FE), 256>>>(ORG, out + FE, FE);
    #undef CG
}

// round 16
// speedup vs baseline: 1.1038x; 1.1038x over previous
#include <cuda_runtime.h>
#include <math.h>
#include <stdint.h>

#define NFULL 6144
#define DF    320
#define NL1   4915
#define NL2   2949
#define NNZ_CAP 2000000
#define FULL_MASK 0xffffffffu

// ---------------- device scratch ----------------
__device__ __align__(128) float g_XA[NFULL*DF];
__device__ __align__(128) float g_XB[NFULL*DF];
__device__ __align__(128) float g_XC[NFULL*DF];
__device__ __align__(128) float g_H [NFULL*DF];
__device__ __align__(128) float g_CAT[NFULL*2*DF];
__device__ __align__(128) float g_ORG[NFULL*DF];
__device__ __align__(128) float g_D0[NFULL*DF];
__device__ __align__(128) float g_D1[NL1*DF];
__device__ float g_SV[NFULL];
__device__ float g_TV[NFULL];
__device__ float g_SC[NFULL];
__device__ float g_VAL[NL1];

__device__ int g_RP0[NFULL+1];
__device__ int g_C0[NNZ_CAP];
__device__ int g_RP1A[NL1+1];
__device__ int g_C1A[NNZ_CAP];
__device__ int g_RP1B[NL1+1];
__device__ int g_C1B[NNZ_CAP];
__device__ int g_RP2[NL2+1];
__device__ int g_C2[NNZ_CAP];
__device__ int g_I1P1[NL1];
__device__ int g_I2P1[NL2];
__device__ int g_IT1[NL1];
__device__ int g_IT2[NL2];
__device__ int g_POS[NFULL];

// ---------------- helpers ----------------
__device__ __forceinline__ float warpSum(float v){
#pragma unroll
    for (int o = 16; o; o >>= 1) v += __shfl_xor_sync(FULL_MASK, v, o);
    return v;
}
__device__ __forceinline__ int warpSumI(int v){
#pragma unroll
    for (int o = 16; o; o >>= 1) v += __shfl_xor_sync(FULL_MASK, v, o);
    return v;
}

// ---------------- CSR build from dense A ----------------
__global__ void k_count0(const float* __restrict__ A, int* __restrict__ cnt){
    int row = blockIdx.x;
    int tid = threadIdx.x;
    const float4* Ar = reinterpret_cast<const float4*>(A + (size_t)row * NFULL);
    int c = 0;
    for (int j = tid; j < NFULL/4; j += 256){
        float4 v = __ldg(&Ar[j]);
        c += (v.x > 0.f) + (v.y > 0.f) + (v.z > 0.f) + (v.w > 0.f);
    }
    c = warpSumI(c);
    __shared__ int sh[8];
    int lane = tid & 31, wid = tid >> 5;
    if (lane == 0) sh[wid] = c;
    __syncthreads();
    if (tid == 0){
        int t = 0;
        for (int i = 0; i < 8; i++) t += sh[i];
        cnt[row] = t;
    }
}

// single-block exclusive scan in place; a[n] = total
__global__ void k_scan(int* a, int n){
    __shared__ int sh[1024];
    __shared__ int carry;
    int tid = threadIdx.x;
    if (tid == 0) carry = 0;
    __syncthreads();
    for (int base = 0; base < n; base += 1024){
        int i = base + tid;
        int v = (i < n) ? a[i] : 0;
        sh[tid] = v;
        __syncthreads();
        for (int off = 1; off < 1024; off <<= 1){
            int t = (tid >= off) ? sh[tid - off] : 0;
            __syncthreads();
            sh[tid] += t;
            __syncthreads();
        }
        if (i < n) a[i] = carry + sh[tid] - v;
        int tot = sh[1023];
        __syncthreads();
        if (tid == 0) carry += tot;
        __syncthreads();
    }
    if (tid == 0) a[n] = carry;
}

// 8 warps per row, each owns a 768-col stripe: count, block-scan, fill
__global__ __launch_bounds__(256) void k_fill0(const float* __restrict__ A, const int* __restrict__ rp,
                                               int* __restrict__ cols){
    int row = blockIdx.x;
    int tid = threadIdx.x, lane = tid & 31, wid = tid >> 5;
    __shared__ int wcnt[8];
    const float* Ar = A + (size_t)row * NFULL;
    int c0 = wid * 768;
    int c = 0;
    for (int j = c0 + lane; j < c0 + 768; j += 32) c += (Ar[j] > 0.f);
    c = warpSumI(c);
    if (lane == 0) wcnt[wid] = c;
    __syncthreads();
    int base = rp[row];
    for (int w = 0; w < wid; w++) base += wcnt[w];
    for (int j0 = c0; j0 < c0 + 768; j0 += 32){
        int j = j0 + lane;
        bool pred = Ar[j] > 0.f;
        unsigned m = __ballot_sync(FULL_MASK, pred);
        if (pred) cols[base + __popc(m & ((1u << lane) - 1u))] = j;
        base += __popc(m);
    }
}

// ---------------- pooled CSR ----------------
__global__ void k_pcount(const int* __restrict__ rpp, const int* __restrict__ colsp,
                         const int* __restrict__ idx, const int* __restrict__ pos,
                         int* __restrict__ cnt){
    int r = blockIdx.x;
    int lane = threadIdx.x;
    int pr = idx[r];
    int s = rpp[pr], e = rpp[pr+1];
    int c = 0;
    for (int i = s + lane; i < e; i += 32) c += (pos[colsp[i]] >= 0);
    c = warpSumI(c);
    if (lane == 0) cnt[r] = c;
}

__global__ void k_pfill(const int* __restrict__ rpp, const int* __restrict__ colsp,
                        const int* __restrict__ idx, const int* __restrict__ pos,
                        const int* __restrict__ rpn, int* __restrict__ colsn){
    int r = blockIdx.x;
    int lane = threadIdx.x;
    int pr = idx[r];
    int s = rpp[pr], e = rpp[pr+1];
    int base = rpn[r];
    for (int i0 = s; i0 < e; i0 += 32){
        int i = i0 + lane;
        int p = -1;
        bool pred = false;
        if (i < e){ p = pos[colsp[i]]; pred = (p >= 0); }
        unsigned m = __ballot_sync(FULL_MASK, pred);
        if (pred) colsn[base + __popc(m & ((1u << lane) - 1u))] = p;
        base += __popc(m);
    }
}

// ---------------- GEMM: C[Mx320] = A[MxK]*B[Kx320] (+bias)(+res) ----------------
// 128x64 tile, 8x4 micro-tile, 256 threads
__global__ __launch_bounds__(256) void k_gemm(const float* __restrict__ A, const float* __restrict__ B,
                                              const float* __restrict__ bias, const float* __restrict__ res,
                                              float* __restrict__ C, int M, int K){
    __shared__ float As[16][128];
    __shared__ float Bs[16][64];
    int tid = threadIdx.x;
    int bm = blockIdx.y * 128, bn = blockIdx.x * 64;
    int tx = tid & 15, ty = tid >> 4;
    int b_k = tid >> 4, b_n = (tid & 15) * 4;
    float acc[8][4];
#pragma unroll
    for (int r = 0; r < 8; r++)
#pragma unroll
        for (int c = 0; c < 4; c++) acc[r][c] = 0.f;

    for (int k0 = 0; k0 < K; k0 += 16){
#pragma unroll
        for (int q = 0; q < 2; q++){
            int f = tid * 2 + q;
            int am = f >> 2, ak = (f & 3) * 4;
            float4 av = make_float4(0.f,0.f,0.f,0.f);
            if (bm + am < M)
                av = *reinterpret_cast<const float4*>(&A[(size_t)(bm + am) * K + k0 + ak]);
            As[ak+0][am] = av.x; As[ak+1][am] = av.y;
            As[ak+2][am] = av.z; As[ak+3][am] = av.w;
        }
        *reinterpret_cast<float4*>(&Bs[b_k][b_n]) =
            *reinterpret_cast<const float4*>(&B[(size_t)(k0 + b_k) * 320 + bn + b_n]);
        __syncthreads();
#pragma unroll
        for (int kk = 0; kk < 16; kk++){
            float4 b4 = *reinterpret_cast<const float4*>(&Bs[kk][tx*4]);
            float4 a0 = *reinterpret_cast<const float4*>(&As[kk][ty*8]);
            float4 a1 = *reinterpret_cast<const float4*>(&As[kk][ty*8+4]);
            float ar[8] = {a0.x,a0.y,a0.z,a0.w,a1.x,a1.y,a1.z,a1.w};
#pragma unroll
            for (int r = 0; r < 8; r++){
                acc[r][0] += ar[r]*b4.x; acc[r][1] += ar[r]*b4.y;
                acc[r][2] += ar[r]*b4.z; acc[r][3] += ar[r]*b4.w;
            }
        }
        __syncthreads();
    }
    float4 bb = make_float4(0.f,0.f,0.f,0.f);
    if (bias) bb = *reinterpret_cast<const float4*>(&bias[bn + tx*4]);
#pragma unroll
    for (int r = 0; r < 8; r++){
        int row = bm + ty*8 + r;
        if (row < M){
            float4 o;
            o.x = acc[r][0] + bb.x; o.y = acc[r][1] + bb.y;
            o.z = acc[r][2] + bb.z; o.w = acc[r][3] + bb.w;
            if (res){
                float4 rr = *reinterpret_cast<const float4*>(&res[(size_t)row * 320 + bn + tx*4]);
                o.x += rr.x; o.y += rr.y; o.z += rr.z; o.w += rr.w;
            }
            *reinterpret_cast<float4*>(&C[(size_t)row * 320 + bn + tx*4]) = o;
        }
    }
}

// ---------------- SpMM: Y[i,:] = sum_{j in nbr(i)} X[j,:] ----------------
__global__ __launch_bounds__(320) void k_spmm(const int* __restrict__ rp, const int* __restrict__ cols,
                                              const float* __restrict__ X, float* __restrict__ Y){
    int row = blockIdx.x;
    int s = rp[row], e = rp[row+1];
    int tid = threadIdx.x;
    __shared__ int cbuf[512];
    float a0 = 0.f, a1 = 0.f, a2 = 0.f, a3 = 0.f;
    for (int c0 = s; c0 < e; c0 += 512){
        int cc = min(512, e - c0);
        __syncthreads();
        for (int i = tid; i < cc; i += 320) cbuf[i] = cols[c0 + i];
        __syncthreads();
        int i = 0;
        for (; i + 3 < cc; i += 4){
            a0 += X[(size_t)cbuf[i]   * 320 + tid];
            a1 += X[(size_t)cbuf[i+1] * 320 + tid];
            a2 += X[(size_t)cbuf[i+2] * 320 + tid];
            a3 += X[(size_t)cbuf[i+3] * 320 + tid];
        }
        for (; i < cc; i++) a0 += X[(size_t)cbuf[i] * 320 + tid];
    }
    Y[(size_t)row * 320 + tid] = (a0 + a1) + (a2 + a3);
}

// ---------------- GAT s,t ----------------
__global__ __launch_bounds__(256) void k_st(const float* __restrict__ h, const float* __restrict__ a,
                                            float* __restrict__ sv, float* __restrict__ tv){
    int row = blockIdx.x;
    int tid = threadIdx.x;
    float ps = 0.f, pt = 0.f;
    for (int f = tid; f < 320; f += 256){
        float v = h[(size_t)row * 320 + f];
        ps += v * a[f];
        pt += v * a[320 + f];
    }
    ps = warpSum(ps); pt = warpSum(pt);
    __shared__ float sh[16];
    int lane = tid & 31, wid = tid >> 5;
    if (lane == 0){ sh[wid] = ps; sh[8 + wid] = pt; }
    __syncthreads();
    if (tid == 0){
        float x = 0.f, y = 0.f;
        for (int i = 0; i < 8; i++){ x += sh[i]; y += sh[8 + i]; }
        sv[row] = x; tv[row] = y;
    }
}

// ---- fused GAT row: online softmax (max+sum in one pass) + weighted gather + elu ----
__global__ __launch_bounds__(320) void k_gat(const int* __restrict__ rp, const int* __restrict__ cols,
                                             const float* __restrict__ h, const float* __restrict__ sv,
                                             const float* __restrict__ tv, float* __restrict__ out){
    int row = blockIdx.x;
    int s = rp[row], e = rp[row+1];
    int tid = threadIdx.x;
    int lane = tid & 31, wid = tid >> 5;
    __shared__ float smx[10], ssm[10], sfin[2];
    __shared__ float wbuf[512];
    __shared__ int   cbuf[512];
    float si = sv[row];

    // single pass: per-thread online (max, sum)
    float m = -1e30f, sm = 0.f;
    for (int i = s + tid; i < e; i += 320){
        float x = si + tv[cols[i]];
        x = x > 0.f ? x : 0.2f * x;
        if (x > m){ sm = sm * expf(m - x) + 1.f; m = x; }
        else       sm += expf(x - m);
    }
    // warp combine
#pragma unroll
    for (int o = 16; o; o >>= 1){
        float mo = __shfl_xor_sync(FULL_MASK, m, o);
        float so = __shfl_xor_sync(FULL_MASK, sm, o);
        float mn = fmaxf(m, mo);
        sm = sm * expf(m - mn) + so * expf(mo - mn);
        m = mn;
    }
    if (lane == 0){ smx[wid] = m; ssm[wid] = sm; }
    __syncthreads();
    if (tid == 0){
        float mm = smx[0];
        for (int i = 1; i < 10; i++) mm = fmaxf(mm, smx[i]);
        float z = 0.f;
        for (int i = 0; i < 10; i++) z += ssm[i] * expf(smx[i] - mm);
        sfin[0] = mm; sfin[1] = 1.f / z;
    }
    __syncthreads();
    m = sfin[0];
    float invZ = sfin[1];

    // weighted gather
    float a0 = 0.f, a1 = 0.f;
    for (int c0 = s; c0 < e; c0 += 512){
        int cc = min(512, e - c0);
        __syncthreads();
        for (int i = tid; i < cc; i += 320){
            int c = cols[c0 + i];
            cbuf[i] = c;
            float x = si + tv[c];
            x = x > 0.f ? x : 0.2f * x;
            wbuf[i] = expf(x - m);
        }
        __syncthreads();
        int i = 0;
        for (; i + 1 < cc; i += 2){
            a0 += wbuf[i]   * h[(size_t)cbuf[i]   * 320 + tid];
            a1 += wbuf[i+1] * h[(size_t)cbuf[i+1] * 320 + tid];
        }
        if (i < cc) a0 += wbuf[i] * h[(size_t)cbuf[i] * 320 + tid];
    }
    float y = (a0 + a1) * invZ;
    out[(size_t)row * 320 + tid] = y > 0.f ? y : expm1f(y);
}

// ---------------- pooling ----------------
__global__ void k_score(const float* __restrict__ X, const float* __restrict__ w,
                        const float* __restrict__ b, float* __restrict__ sc, int M){
    int row = blockIdx.x * 8 + (threadIdx.x >> 5);
    int lane = threadIdx.x & 31;
    if (row >= M) return;
    float s = 0.f;
    for (int f = lane; f < 320; f += 32) s += X[(size_t)row * 320 + f] * w[f];
    s = warpSum(s);
    if (lane == 0) sc[row] = 1.f / (1.f + expf(-(s + b[0]) / 100.f));
}

// rank-by-counting top-k: exact descending order, ties -> smaller index first
__global__ __launch_bounds__(256) void k_rank_topk(const float* __restrict__ scores, int n, int knum,
                                                   int* __restrict__ idx, float* __restrict__ vals){
    __shared__ float sk[NFULL];
    int tid = threadIdx.x;
    for (int i = tid; i < n; i += 256) sk[i] = scores[i];
    __syncthreads();
    int i = blockIdx.x * 256 + tid;
    if (i >= n) return;
    float si = sk[i];
    int rank = 0;
    for (int j = 0; j < n; j++){
        float sj = sk[j];
        rank += (sj > si) || (sj == si && j < i);
    }
    if (rank < knum){ idx[rank] = i; vals[rank] = si; }
}

__global__ void k_gate(const float* __restrict__ X, const int* __restrict__ idx,
                       const float* __restrict__ vals, float* __restrict__ Y){
    int r = blockIdx.x, f = threadIdx.x;
    Y[(size_t)r * 320 + f] = X[(size_t)idx[r] * 320 + f] * vals[r];
}

__global__ void k_ineg(int* p, int n){
    int i = blockIdx.x * 256 + threadIdx.x;
    if (i < n) p[i] = -1;
}
__global__ void k_setpos(const int* __restrict__ idx, int* __restrict__ p, int k){
    int i = blockIdx.x * 256 + threadIdx.x;
    if (i < k) p[idx[i]] = i;
}
__global__ void k_zero(float* p, int n){
    int i = blockIdx.x * 256 + threadIdx.x;
    if (i < n) p[i] = 0.f;
}
__global__ void k_scatter(const float* __restrict__ X, const int* __restrict__ idx,
                          float* __restrict__ Y){
    int r = blockIdx.x, f = threadIdx.x;
    Y[(size_t)idx[r] * 320 + f] = X[(size_t)r * 320 + f];
}
__global__ void k_copyf(const float* __restrict__ s, float* __restrict__ d, int n){
    int i = blockIdx.x * 256 + threadIdx.x;
    if (i < n) d[i] = s[i];
}
__global__ void k_copyi(const int* __restrict__ s, int* __restrict__ d, int n){
    int i = blockIdx.x * 256 + threadIdx.x;
    if (i < n) d[i] = s[i];
}
__global__ void k_concat(const float* __restrict__ X, const float* __restrict__ O,
                         float* __restrict__ C){
    int r = blockIdx.x, f = threadIdx.x;
    C[(size_t)r * 640 + f]       = X[(size_t)r * 320 + f];
    C[(size_t)r * 640 + 320 + f] = O[(size_t)r * 320 + f];
}

// ---------------- orchestration ----------------
static void gemm(const float* A, const float* B, const float* bias, const float* res,
                 float* C, int M, int K){
    dim3 g(5, (M + 127) / 128);
    k_gemm<<<g, 256>>>(A, B, bias, res, C, M, K);
}

extern "C" void kernel_launch(void* const* d_in, const int* in_sizes, int n_in,
                              void* d_out, int out_size) {
    const float* Aden  = (const float*)d_in[0];
    const float* Xin   = (const float*)d_in[1];
    const float* sg_W  = (const float*)d_in[2];
    const float* sg_a  = (const float*)d_in[3];
    const float* bg_W  = (const float*)d_in[4];
    const float* bg_a  = (const float*)d_in[5];
    const float* eg_W  = (const float*)d_in[6];
    const float* eg_a  = (const float*)d_in[7];
    const float* dn_W  = (const float*)d_in[8];
    const float* dn_b  = (const float*)d_in[9];
    const float* up_W  = (const float*)d_in[10];
    const float* up_b  = (const float*)d_in[11];
    const float* pl_w  = (const float*)d_in[12];
    const float* pl_b  = (const float*)d_in[13];
    float* out = (float*)d_out;

    void* p;
    cudaGetSymbolAddress(&p, g_XA);  float* XA = (float*)p;
    cudaGetSymbolAddress(&p, g_XB);  float* XB = (float*)p;
    cudaGetSymbolAddress(&p, g_XC);  float* XC = (float*)p;
    cudaGetSymbolAddress(&p, g_H);   float* H  = (float*)p;
    cudaGetSymbolAddress(&p, g_CAT); float* CAT = (float*)p;
    cudaGetSymbolAddress(&p, g_ORG); float* ORG = (float*)p;
    cudaGetSymbolAddress(&p, g_D0);  float* D0 = (float*)p;
    cudaGetSymbolAddress(&p, g_D1);  float* D1 = (float*)p;
    cudaGetSymbolAddress(&p, g_SV);  float* SV = (float*)p;
    cudaGetSymbolAddress(&p, g_TV);  float* TV = (float*)p;
    cudaGetSymbolAddress(&p, g_SC);  float* SC = (float*)p;
    cudaGetSymbolAddress(&p, g_VAL); float* VAL = (float*)p;
    cudaGetSymbolAddress(&p, g_RP0); int* RP0 = (int*)p;
    cudaGetSymbolAddress(&p, g_C0);  int* C0  = (int*)p;
    cudaGetSymbolAddress(&p, g_RP1A);int* RP1A = (int*)p;
    cudaGetSymbolAddress(&p, g_C1A); int* C1A = (int*)p;
    cudaGetSymbolAddress(&p, g_RP1B);int* RP1B = (int*)p;
    cudaGetSymbolAddress(&p, g_C1B); int* C1B = (int*)p;
    cudaGetSymbolAddress(&p, g_RP2); int* RP2 = (int*)p;
    cudaGetSymbolAddress(&p, g_C2);  int* C2  = (int*)p;
    cudaGetSymbolAddress(&p, g_I1P1);int* I1P1 = (int*)p;
    cudaGetSymbolAddress(&p, g_I2P1);int* I2P1 = (int*)p;
    cudaGetSymbolAddress(&p, g_IT1); int* IT1 = (int*)p;
    cudaGetSymbolAddress(&p, g_IT2); int* IT2 = (int*)p;
    cudaGetSymbolAddress(&p, g_POS); int* POS = (int*)p;

    const int FE = NFULL * DF;
    const int E1 = NL1 * DF;
    #define CG(n) (((n) + 255) / 256)

    // CSR of full A
    k_count0<<<NFULL, 256>>>(Aden, RP0);
    k_scan<<<1, 1024>>>(RP0, NFULL);
    k_fill0<<<NFULL, 256>>>(Aden, RP0, C0);

    // start GAT (sg)
    gemm(Xin, sg_W, nullptr, nullptr, H, NFULL, 320);
    k_st<<<NFULL, 256>>>(H, sg_a, SV, TV);
    k_gat<<<NFULL, 320>>>(RP0, C0, H, SV, TV, XA);
    k_copyf<<<CG(FE), 256>>>(XA, ORG, FE);

    for (int pass = 0; pass < 2; pass++){
        int* RP1 = pass == 0 ? RP1A : RP1B;
        int* C1  = pass == 0 ? C1A  : C1B;

        // ---- down level 0 (full) ----
        k_spmm<<<NFULL, 320>>>(RP0, C0, XA, XB);
        gemm(XB, dn_W, dn_b, nullptr, XC, NFULL, 320);
        if (pass == 0) k_copyf<<<CG(FE), 256>>>(XC, D0, FE);

        // pool 1: 6144 -> 4915
        k_score<<<(NFULL + 7) / 8, 256>>>(XC, pl_w, pl_b, SC, NFULL);
        k_rank_topk<<<CG(NFULL), 256>>>(SC, NFULL, NL1, IT1, VAL);
        if (pass == 0) k_copyi<<<CG(NL1), 256>>>(IT1, I1P1, NL1);
        k_gate<<<NL1, 320>>>(XC, IT1, VAL, XA);
        k_ineg<<<CG(NFULL), 256>>>(POS, NFULL);
        k_setpos<<<CG(NL1), 256>>>(IT1, POS, NL1);
        k_pcount<<<NL1, 32>>>(RP0, C0, IT1, POS, RP1);
        k_scan<<<1, 1024>>>(RP1, NL1);
        k_pfill<<<NL1, 32>>>(RP0, C0, IT1, POS, RP1, C1);

        // ---- down level 1 ----
        k_spmm<<<NL1, 320>>>(RP1, C1, XA, XB);
        gemm(XB, dn_W + 320*320, dn_b + 320, nullptr, XC, NL1, 320);
        if (pass == 0) k_copyf<<<CG(E1), 256>>>(XC, D1, E1);

        // pool 2: 4915 -> 2949
        k_score<<<(NL1 + 7) / 8, 256>>>(XC, pl_w + 320, pl_b + 1, SC, NL1);
        k_rank_topk<<<CG(NL1), 256>>>(SC, NL1, NL2, IT2, VAL);
        if (pass == 0) k_copyi<<<CG(NL2), 256>>>(IT2, I2P1, NL2);
        k_gate<<<NL2, 320>>>(XC, IT2, VAL, XA);
        k_ineg<<<CG(NL1), 256>>>(POS, NL1);
        k_setpos<<<CG(NL2), 256>>>(IT2, POS, NL2);
        k_pcount<<<NL2, 32>>>(RP1, C1, IT2, POS, RP2);
        k_scan<<<1, 1024>>>(RP2, NL2);
        k_pfill<<<NL2, 32>>>(RP1, C1, IT2, POS, RP2, C2);

        // ---- bottom GAT (bg) ----
        gemm(XA, bg_W, nullptr, nullptr, H, NL2, 320);
        k_st<<<NL2, 256>>>(H, bg_a, SV, TV);
        k_gat<<<NL2, 320>>>(RP2, C2, H, SV, TV, XB);

        // ---- up i=0 (uses pass-1 level-1 structures) ----
        k_zero<<<CG(E1), 256>>>(XA, E1);
        k_scatter<<<NL2, 320>>>(XB, I2P1, XA);
        k_spmm<<<NL1, 320>>>(RP1A, C1A, XA, XC);
        gemm(XC, up_W, up_b, D1, XB, NL1, 320);

        // ---- up i=1 (full) ----
        k_zero<<<CG(FE), 256>>>(XA, FE);
        k_scatter<<<NL1, 320>>>(XB, I1P1, XA);
        k_spmm<<<NFULL, 320>>>(RP0, C0, XA, XC);
        gemm(XC, up_W + 320*320, up_b + 320, D0, XB, NFULL, 320);

        // ---- concat + end GAT (eg) ----
        k_concat<<<NFULL, 320>>>(XB, ORG, CAT);
        gemm(CAT, eg_W, nullptr, nullptr, H, NFULL, 640);
        k_st<<<NFULL, 256>>>(H, eg_a, SV, TV);
        k_gat<<<NFULL, 320>>>(RP0, C0, H, SV, TV, XA);
    }

    // outputs: (X, start)
    k_copyf<<<CG(FE), 256>>>(XA, out, FE);
    k_copyf<<<CG(FE), 256>>>(ORG, out + FE, FE);
    #undef CG
}

// round 17
// speedup vs baseline: 1.1043x; 1.0004x over previous
#include <cuda_runtime.h>
#include <math.h>
#include <stdint.h>

#define NFULL 6144
#define DF    320
#define NL1   4915
#define NL2   2949
#define NNZ_CAP 2000000
#define FULL_MASK 0xffffffffu

// ---------------- device scratch ----------------
__device__ __align__(128) float g_XA[NFULL*DF];
__device__ __align__(128) float g_XB[NFULL*DF];
__device__ __align__(128) float g_XC[NFULL*DF];
__device__ __align__(128) float g_H [NFULL*DF];
__device__ __align__(128) float g_CAT[NFULL*2*DF];
__device__ __align__(128) float g_ORG[NFULL*DF];
__device__ __align__(128) float g_D0[NFULL*DF];
__device__ __align__(128) float g_D1[NL1*DF];
__device__ float g_SV[NFULL];
__device__ float g_TV[NFULL];
__device__ float g_SC[NFULL];
__device__ float g_VAL[NL1];

__device__ int g_RP0[NFULL+1];
__device__ int g_C0[NNZ_CAP];
__device__ int g_RP1A[NL1+1];
__device__ int g_C1A[NNZ_CAP];
__device__ int g_RP1B[NL1+1];
__device__ int g_C1B[NNZ_CAP];
__device__ int g_RP2[NL2+1];
__device__ int g_C2[NNZ_CAP];
__device__ int g_I1P1[NL1];
__device__ int g_I2P1[NL2];
__device__ int g_IT1[NL1];
__device__ int g_IT2[NL2];
__device__ int g_POS[NFULL];

// ---------------- helpers ----------------
__device__ __forceinline__ float warpSum(float v){
#pragma unroll
    for (int o = 16; o; o >>= 1) v += __shfl_xor_sync(FULL_MASK, v, o);
    return v;
}
__device__ __forceinline__ int warpSumI(int v){
#pragma unroll
    for (int o = 16; o; o >>= 1) v += __shfl_xor_sync(FULL_MASK, v, o);
    return v;
}

// ---------------- CSR build from dense A ----------------
__global__ void k_count0(const float* __restrict__ A, int* __restrict__ cnt){
    int row = blockIdx.x;
    int tid = threadIdx.x;
    const float4* Ar = reinterpret_cast<const float4*>(A + (size_t)row * NFULL);
    int c = 0;
    for (int j = tid; j < NFULL/4; j += 256){
        float4 v = __ldg(&Ar[j]);
        c += (v.x > 0.f) + (v.y > 0.f) + (v.z > 0.f) + (v.w > 0.f);
    }
    c = warpSumI(c);
    __shared__ int sh[8];
    int lane = tid & 31, wid = tid >> 5;
    if (lane == 0) sh[wid] = c;
    __syncthreads();
    if (tid == 0){
        int t = 0;
        for (int i = 0; i < 8; i++) t += sh[i];
        cnt[row] = t;
    }
}

// single-block exclusive scan in place; a[n] = total
__global__ void k_scan(int* a, int n){
    __shared__ int sh[1024];
    __shared__ int carry;
    int tid = threadIdx.x;
    if (tid == 0) carry = 0;
    __syncthreads();
    for (int base = 0; base < n; base += 1024){
        int i = base + tid;
        int v = (i < n) ? a[i] : 0;
        sh[tid] = v;
        __syncthreads();
        for (int off = 1; off < 1024; off <<= 1){
            int t = (tid >= off) ? sh[tid - off] : 0;
            __syncthreads();
            sh[tid] += t;
            __syncthreads();
        }
        if (i < n) a[i] = carry + sh[tid] - v;
        int tot = sh[1023];
        __syncthreads();
        if (tid == 0) carry += tot;
        __syncthreads();
    }
    if (tid == 0) a[n] = carry;
}

// 8 warps per row, each owns a 768-col stripe: count, block-scan, fill
__global__ __launch_bounds__(256) void k_fill0(const float* __restrict__ A, const int* __restrict__ rp,
                                               int* __restrict__ cols){
    int row = blockIdx.x;
    int tid = threadIdx.x, lane = tid & 31, wid = tid >> 5;
    __shared__ int wcnt[8];
    const float* Ar = A + (size_t)row * NFULL;
    int c0 = wid * 768;
    int c = 0;
    for (int j = c0 + lane; j < c0 + 768; j += 32) c += (Ar[j] > 0.f);
    c = warpSumI(c);
    if (lane == 0) wcnt[wid] = c;
    __syncthreads();
    int base = rp[row];
    for (int w = 0; w < wid; w++) base += wcnt[w];
    for (int j0 = c0; j0 < c0 + 768; j0 += 32){
        int j = j0 + lane;
        bool pred = Ar[j] > 0.f;
        unsigned m = __ballot_sync(FULL_MASK, pred);
        if (pred) cols[base + __popc(m & ((1u << lane) - 1u))] = j;
        base += __popc(m);
    }
}

// ---------------- pooled CSR ----------------
__global__ void k_pcount(const int* __restrict__ rpp, const int* __restrict__ colsp,
                         const int* __restrict__ idx, const int* __restrict__ pos,
                         int* __restrict__ cnt){
    int r = blockIdx.x;
    int lane = threadIdx.x;
    int pr = idx[r];
    int s = rpp[pr], e = rpp[pr+1];
    int c = 0;
    for (int i = s + lane; i < e; i += 32) c += (pos[colsp[i]] >= 0);
    c = warpSumI(c);
    if (lane == 0) cnt[r] = c;
}

__global__ void k_pfill(const int* __restrict__ rpp, const int* __restrict__ colsp,
                        const int* __restrict__ idx, const int* __restrict__ pos,
                        const int* __restrict__ rpn, int* __restrict__ colsn){
    int r = blockIdx.x;
    int lane = threadIdx.x;
    int pr = idx[r];
    int s = rpp[pr], e = rpp[pr+1];
    int base = rpn[r];
    for (int i0 = s; i0 < e; i0 += 32){
        int i = i0 + lane;
        int p = -1;
        bool pred = false;
        if (i < e){ p = pos[colsp[i]]; pred = (p >= 0); }
        unsigned m = __ballot_sync(FULL_MASK, pred);
        if (pred) colsn[base + __popc(m & ((1u << lane) - 1u))] = p;
        base += __popc(m);
    }
}

// ---------------- GEMM: C[Mx320] = A[MxK]*B[Kx320] (+bias)(+res) ----------------
// 128x64 tile, 8x4 micro-tile, 256 threads
__global__ __launch_bounds__(256) void k_gemm(const float* __restrict__ A, const float* __restrict__ B,
                                              const float* __restrict__ bias, const float* __restrict__ res,
                                              float* __restrict__ C, int M, int K){
    __shared__ float As[16][128];
    __shared__ float Bs[16][64];
    int tid = threadIdx.x;
    int bm = blockIdx.y * 128, bn = blockIdx.x * 64;
    int tx = tid & 15, ty = tid >> 4;
    int b_k = tid >> 4, b_n = (tid & 15) * 4;
    float acc[8][4];
#pragma unroll
    for (int r = 0; r < 8; r++)
#pragma unroll
        for (int c = 0; c < 4; c++) acc[r][c] = 0.f;

    for (int k0 = 0; k0 < K; k0 += 16){
#pragma unroll
        for (int q = 0; q < 2; q++){
            int f = tid * 2 + q;
            int am = f >> 2, ak = (f & 3) * 4;
            float4 av = make_float4(0.f,0.f,0.f,0.f);
            if (bm + am < M)
                av = *reinterpret_cast<const float4*>(&A[(size_t)(bm + am) * K + k0 + ak]);
            As[ak+0][am] = av.x; As[ak+1][am] = av.y;
            As[ak+2][am] = av.z; As[ak+3][am] = av.w;
        }
        *reinterpret_cast<float4*>(&Bs[b_k][b_n]) =
            *reinterpret_cast<const float4*>(&B[(size_t)(k0 + b_k) * 320 + bn + b_n]);
        __syncthreads();
#pragma unroll
        for (int kk = 0; kk < 16; kk++){
            float4 b4 = *reinterpret_cast<const float4*>(&Bs[kk][tx*4]);
            float4 a0 = *reinterpret_cast<const float4*>(&As[kk][ty*8]);
            float4 a1 = *reinterpret_cast<const float4*>(&As[kk][ty*8+4]);
            float ar[8] = {a0.x,a0.y,a0.z,a0.w,a1.x,a1.y,a1.z,a1.w};
#pragma unroll
            for (int r = 0; r < 8; r++){
                acc[r][0] += ar[r]*b4.x; acc[r][1] += ar[r]*b4.y;
                acc[r][2] += ar[r]*b4.z; acc[r][3] += ar[r]*b4.w;
            }
        }
        __syncthreads();
    }
    float4 bb = make_float4(0.f,0.f,0.f,0.f);
    if (bias) bb = *reinterpret_cast<const float4*>(&bias[bn + tx*4]);
#pragma unroll
    for (int r = 0; r < 8; r++){
        int row = bm + ty*8 + r;
        if (row < M){
            float4 o;
            o.x = acc[r][0] + bb.x; o.y = acc[r][1] + bb.y;
            o.z = acc[r][2] + bb.z; o.w = acc[r][3] + bb.w;
            if (res){
                float4 rr = *reinterpret_cast<const float4*>(&res[(size_t)row * 320 + bn + tx*4]);
                o.x += rr.x; o.y += rr.y; o.z += rr.z; o.w += rr.w;
            }
            *reinterpret_cast<float4*>(&C[(size_t)row * 320 + bn + tx*4]) = o;
        }
    }
}

// ---------------- SpMM: Y[i,:] = sum_{j in nbr(i)} X[j,:] ----------------
__global__ __launch_bounds__(320) void k_spmm(const int* __restrict__ rp, const int* __restrict__ cols,
                                              const float* __restrict__ X, float* __restrict__ Y){
    int row = blockIdx.x;
    int s = rp[row], e = rp[row+1];
    int tid = threadIdx.x;
    __shared__ int cbuf[512];
    float a0 = 0.f, a1 = 0.f, a2 = 0.f, a3 = 0.f;
    for (int c0 = s; c0 < e; c0 += 512){
        int cc = min(512, e - c0);
        __syncthreads();
        for (int i = tid; i < cc; i += 320) cbuf[i] = cols[c0 + i];
        __syncthreads();
        int i = 0;
        for (; i + 3 < cc; i += 4){
            a0 += X[(size_t)cbuf[i]   * 320 + tid];
            a1 += X[(size_t)cbuf[i+1] * 320 + tid];
            a2 += X[(size_t)cbuf[i+2] * 320 + tid];
            a3 += X[(size_t)cbuf[i+3] * 320 + tid];
        }
        for (; i < cc; i++) a0 += X[(size_t)cbuf[i] * 320 + tid];
    }
    Y[(size_t)row * 320 + tid] = (a0 + a1) + (a2 + a3);
}

// ---------------- GAT s,t ----------------
__global__ __launch_bounds__(256) void k_st(const float* __restrict__ h, const float* __restrict__ a,
                                            float* __restrict__ sv, float* __restrict__ tv){
    int row = blockIdx.x;
    int tid = threadIdx.x;
    float ps = 0.f, pt = 0.f;
    for (int f = tid; f < 320; f += 256){
        float v = h[(size_t)row * 320 + f];
        ps += v * a[f];
        pt += v * a[320 + f];
    }
    ps = warpSum(ps); pt = warpSum(pt);
    __shared__ float sh[16];
    int lane = tid & 31, wid = tid >> 5;
    if (lane == 0){ sh[wid] = ps; sh[8 + wid] = pt; }
    __syncthreads();
    if (tid == 0){
        float x = 0.f, y = 0.f;
        for (int i = 0; i < 8; i++){ x += sh[i]; y += sh[8 + i]; }
        sv[row] = x; tv[row] = y;
    }
}

// ---- fused GAT row: online softmax (max+sum in one pass) + weighted gather + elu ----
__global__ __launch_bounds__(320) void k_gat(const int* __restrict__ rp, const int* __restrict__ cols,
                                             const float* __restrict__ h, const float* __restrict__ sv,
                                             const float* __restrict__ tv, float* __restrict__ out){
    int row = blockIdx.x;
    int s = rp[row], e = rp[row+1];
    int tid = threadIdx.x;
    int lane = tid & 31, wid = tid >> 5;
    __shared__ float smx[10], ssm[10], sfin[2];
    __shared__ float wbuf[512];
    __shared__ int   cbuf[512];
    float si = sv[row];

    // single pass: per-thread online (max, sum)
    float m = -1e30f, sm = 0.f;
    for (int i = s + tid; i < e; i += 320){
        float x = si + tv[cols[i]];
        x = x > 0.f ? x : 0.2f * x;
        if (x > m){ sm = sm * expf(m - x) + 1.f; m = x; }
        else       sm += expf(x - m);
    }
    // warp combine
#pragma unroll
    for (int o = 16; o; o >>= 1){
        float mo = __shfl_xor_sync(FULL_MASK, m, o);
        float so = __shfl_xor_sync(FULL_MASK, sm, o);
        float mn = fmaxf(m, mo);
        sm = sm * expf(m - mn) + so * expf(mo - mn);
        m = mn;
    }
    if (lane == 0){ smx[wid] = m; ssm[wid] = sm; }
    __syncthreads();
    if (tid == 0){
        float mm = smx[0];
        for (int i = 1; i < 10; i++) mm = fmaxf(mm, smx[i]);
        float z = 0.f;
        for (int i = 0; i < 10; i++) z += ssm[i] * expf(smx[i] - mm);
        sfin[0] = mm; sfin[1] = 1.f / z;
    }
    __syncthreads();
    m = sfin[0];
    float invZ = sfin[1];

    // weighted gather
    float a0 = 0.f, a1 = 0.f;
    for (int c0 = s; c0 < e; c0 += 512){
        int cc = min(512, e - c0);
        __syncthreads();
        for (int i = tid; i < cc; i += 320){
            int c = cols[c0 + i];
            cbuf[i] = c;
            float x = si + tv[c];
            x = x > 0.f ? x : 0.2f * x;
            wbuf[i] = expf(x - m);
        }
        __syncthreads();
        int i = 0;
        for (; i + 1 < cc; i += 2){
            a0 += wbuf[i]   * h[(size_t)cbuf[i]   * 320 + tid];
            a1 += wbuf[i+1] * h[(size_t)cbuf[i+1] * 320 + tid];
        }
        if (i < cc) a0 += wbuf[i] * h[(size_t)cbuf[i] * 320 + tid];
    }
    float y = (a0 + a1) * invZ;
    out[(size_t)row * 320 + tid] = y > 0.f ? y : expm1f(y);
}

// ---------------- pooling ----------------
__global__ void k_score(const float* __restrict__ X, const float* __restrict__ w,
                        const float* __restrict__ b, float* __restrict__ sc, int M){
    int row = blockIdx.x * 8 + (threadIdx.x >> 5);
    int lane = threadIdx.x & 31;
    if (row >= M) return;
    float s = 0.f;
    for (int f = lane; f < 320; f += 32) s += X[(size_t)row * 320 + f] * w[f];
    s = warpSum(s);
    if (lane == 0) sc[row] = 1.f / (1.f + expf(-(s + b[0]) / 100.f));
}

// rank-by-counting top-k: exact descending order, ties -> smaller index first
__global__ __launch_bounds__(256) void k_rank_topk(const float* __restrict__ scores, int n, int knum,
                                                   int* __restrict__ idx, float* __restrict__ vals){
    __shared__ float sk[NFULL];
    int tid = threadIdx.x;
    for (int i = tid; i < n; i += 256) sk[i] = scores[i];
    __syncthreads();
    int i = blockIdx.x * 256 + tid;
    if (i >= n) return;
    float si = sk[i];
    int rank = 0;
    for (int j = 0; j < n; j++){
        float sj = sk[j];
        rank += (sj > si) || (sj == si && j < i);
    }
    if (rank < knum){ idx[rank] = i; vals[rank] = si; }
}

__global__ void k_gate(const float* __restrict__ X, const int* __restrict__ idx,
                       const float* __restrict__ vals, float* __restrict__ Y){
    int r = blockIdx.x, f = threadIdx.x;
    Y[(size_t)r * 320 + f] = X[(size_t)idx[r] * 320 + f] * vals[r];
}

__global__ void k_ineg(int* p, int n){
    int i = blockIdx.x * 256 + threadIdx.x;
    if (i < n) p[i] = -1;
}
__global__ void k_setpos(const int* __restrict__ idx, int* __restrict__ p, int k){
    int i = blockIdx.x * 256 + threadIdx.x;
    if (i < k) p[idx[i]] = i;
}
__global__ void k_zero(float* p, int n){
    int i = blockIdx.x * 256 + threadIdx.x;
    if (i < n) p[i] = 0.f;
}
__global__ void k_scatter(const float* __restrict__ X, const int* __restrict__ idx,
                          float* __restrict__ Y){
    int r = blockIdx.x, f = threadIdx.x;
    Y[(size_t)idx[r] * 320 + f] = X[(size_t)r * 320 + f];
}
__global__ void k_copyf(const float* __restrict__ s, float* __restrict__ d, int n){
    int i = blockIdx.x * 256 + threadIdx.x;
    if (i < n) d[i] = s[i];
}
__global__ void k_copyi(const int* __restrict__ s, int* __restrict__ d, int n){
    int i = blockIdx.x * 256 + threadIdx.x;
    if (i < n) d[i] = s[i];
}
__global__ void k_concat(const float* __restrict__ X, const float* __restrict__ O,
                         float* __restrict__ C){
    int r = blockIdx.x, f = threadIdx.x;
    C[(size_t)r * 640 + f]       = X[(size_t)r * 320 + f];
    C[(size_t)r * 640 + 320 + f] = O[(size_t)r * 320 + f];
}

// ---------------- orchestration ----------------
static void gemm(const float* A, const float* B, const float* bias, const float* res,
                 float* C, int M, int K){
    dim3 g(5, (M + 127) / 128);
    k_gemm<<<g, 256>>>(A, B, bias, res, C, M, K);
}

extern "C" void kernel_launch(void* const* d_in, const int* in_sizes, int n_in,
                              void* d_out, int out_size) {
    const float* Aden  = (const float*)d_in[0];
    const float* Xin   = (const float*)d_in[1];
    const float* sg_W  = (const float*)d_in[2];
    const float* sg_a  = (const float*)d_in[3];
    const float* bg_W  = (const float*)d_in[4];
    const float* bg_a  = (const float*)d_in[5];
    const float* eg_W  = (const float*)d_in[6];
    const float* eg_a  = (const float*)d_in[7];
    const float* dn_W  = (const float*)d_in[8];
    const float* dn_b  = (const float*)d_in[9];
    const float* up_W  = (const float*)d_in[10];
    const float* up_b  = (const float*)d_in[11];
    const float* pl_w  = (const float*)d_in[12];
    const float* pl_b  = (const float*)d_in[13];
    float* out = (float*)d_out;

    void* p;
    cudaGetSymbolAddress(&p, g_XA);  float* XA = (float*)p;
    cudaGetSymbolAddress(&p, g_XB);  float* XB = (float*)p;
    cudaGetSymbolAddress(&p, g_XC);  float* XC = (float*)p;
    cudaGetSymbolAddress(&p, g_H);   float* H  = (float*)p;
    cudaGetSymbolAddress(&p, g_CAT); float* CAT = (float*)p;
    cudaGetSymbolAddress(&p, g_ORG); float* ORG = (float*)p;
    cudaGetSymbolAddress(&p, g_D0);  float* D0 = (float*)p;
    cudaGetSymbolAddress(&p, g_D1);  float* D1 = (float*)p;
    cudaGetSymbolAddress(&p, g_SV);  float* SV = (float*)p;
    cudaGetSymbolAddress(&p, g_TV);  float* TV = (float*)p;
    cudaGetSymbolAddress(&p, g_SC);  float* SC = (float*)p;
    cudaGetSymbolAddress(&p, g_VAL); float* VAL = (float*)p;
    cudaGetSymbolAddress(&p, g_RP0); int* RP0 = (int*)p;
    cudaGetSymbolAddress(&p, g_C0);  int* C0  = (int*)p;
    cudaGetSymbolAddress(&p, g_RP1A);int* RP1A = (int*)p;
    cudaGetSymbolAddress(&p, g_C1A); int* C1A = (int*)p;
    cudaGetSymbolAddress(&p, g_RP1B);int* RP1B = (int*)p;
    cudaGetSymbolAddress(&p, g_C1B); int* C1B = (int*)p;
    cudaGetSymbolAddress(&p, g_RP2); int* RP2 = (int*)p;
    cudaGetSymbolAddress(&p, g_C2);  int* C2  = (int*)p;
    cudaGetSymbolAddress(&p, g_I1P1);int* I1P1 = (int*)p;
    cudaGetSymbolAddress(&p, g_I2P1);int* I2P1 = (int*)p;
    cudaGetSymbolAddress(&p, g_IT1); int* IT1 = (int*)p;
    cudaGetSymbolAddress(&p, g_IT2); int* IT2 = (int*)p;
    cudaGetSymbolAddress(&p, g_POS); int* POS = (int*)p;

    const int FE = NFULL * DF;
    const int E1 = NL1 * DF;
    #define CG(n) (((n) + 255) / 256)

    // CSR of full A
    k_count0<<<NFULL, 256>>>(Aden, RP0);
    k_scan<<<1, 1024>>>(RP0, NFULL);
    k_fill0<<<NFULL, 256>>>(Aden, RP0, C0);

    // start GAT (sg)
    gemm(Xin, sg_W, nullptr, nullptr, H, NFULL, 320);
    k_st<<<NFULL, 256>>>(H, sg_a, SV, TV);
    k_gat<<<NFULL, 320>>>(RP0, C0, H, SV, TV, XA);
    k_copyf<<<CG(FE), 256>>>(XA, ORG, FE);

    for (int pass = 0; pass < 2; pass++){
        int* RP1 = pass == 0 ? RP1A : RP1B;
        int* C1  = pass == 0 ? C1A  : C1B;

        // ---- down level 0 (full) ----
        k_spmm<<<NFULL, 320>>>(RP0, C0, XA, XB);
        gemm(XB, dn_W, dn_b, nullptr, XC, NFULL, 320);
        if (pass == 0) k_copyf<<<CG(FE), 256>>>(XC, D0, FE);

        // pool 1: 6144 -> 4915
        k_score<<<(NFULL + 7) / 8, 256>>>(XC, pl_w, pl_b, SC, NFULL);
        k_rank_topk<<<CG(NFULL), 256>>>(SC, NFULL, NL1, IT1, VAL);
        if (pass == 0) k_copyi<<<CG(NL1), 256>>>(IT1, I1P1, NL1);
        k_gate<<<NL1, 320>>>(XC, IT1, VAL, XA);
        k_ineg<<<CG(NFULL), 256>>>(POS, NFULL);
        k_setpos<<<CG(NL1), 256>>>(IT1, POS, NL1);
        k_pcount<<<NL1, 32>>>(RP0, C0, IT1, POS, RP1);
        k_scan<<<1, 1024>>>(RP1, NL1);
        k_pfill<<<NL1, 32>>>(RP0, C0, IT1, POS, RP1, C1);

        // ---- down level 1 ----
        k_spmm<<<NL1, 320>>>(RP1, C1, XA, XB);
        gemm(XB, dn_W + 320*320, dn_b + 320, nullptr, XC, NL1, 320);
        if (pass == 0) k_copyf<<<CG(E1), 256>>>(XC, D1, E1);

        // pool 2: 4915 -> 2949
        k_score<<<(NL1 + 7) / 8, 256>>>(XC, pl_w + 320, pl_b + 1, SC, NL1);
        k_rank_topk<<<CG(NL1), 256>>>(SC, NL1, NL2, IT2, VAL);
        if (pass == 0) k_copyi<<<CG(NL2), 256>>>(IT2, I2P1, NL2);
        k_gate<<<NL2, 320>>>(XC, IT2, VAL, XA);
        k_ineg<<<CG(NL1), 256>>>(POS, NL1);
        k_setpos<<<CG(NL2), 256>>>(IT2, POS, NL2);
        k_pcount<<<NL2, 32>>>(RP1, C1, IT2, POS, RP2);
        k_scan<<<1, 1024>>>(RP2, NL2);
        k_pfill<<<NL2, 32>>>(RP1, C1, IT2, POS, RP2, C2);

        // ---- bottom GAT (bg) ----
        gemm(XA, bg_W, nullptr, nullptr, H, NL2, 320);
        k_st<<<NL2, 256>>>(H, bg_a, SV, TV);
        k_gat<<<NL2, 320>>>(RP2, C2, H, SV, TV, XB);

        // ---- up i=0 (uses pass-1 level-1 structures) ----
        k_zero<<<CG(E1), 256>>>(XA, E1);
        k_scatter<<<NL2, 320>>>(XB, I2P1, XA);
        k_spmm<<<NL1, 320>>>(RP1A, C1A, XA, XC);
        gemm(XC, up_W, up_b, D1, XB, NL1, 320);

        // ---- up i=1 (full) ----
        k_zero<<<CG(FE), 256>>>(XA, FE);
        k_scatter<<<NL1, 320>>>(XB, I1P1, XA);
        k_spmm<<<NFULL, 320>>>(RP0, C0, XA, XC);
        gemm(XC, up_W + 320*320, up_b + 320, D0, XB, NFULL, 320);

        // ---- concat + end GAT (eg) ----
        k_concat<<<NFULL, 320>>>(XB, ORG, CAT);
        gemm(CAT, eg_W, nullptr, nullptr, H, NFULL, 640);
        k_st<<<NFULL, 256>>>(H, eg_a, SV, TV);
        k_gat<<<NFULL, 320>>>(RP0, C0, H, SV, TV, XA);
    }

    // outputs: (X, start)
    k_copyf<<<CG(FE), 256>>>(XA, out, FE);
    k_copyf<<<CG(FE), 256>>>(ORG, out + FE, FE);
    #undef CG
}